// round 14
// baseline (speedup 1.0000x reference)
#include <cuda_runtime.h>
#include <cuda_bf16.h>
#include <cstdint>

typedef __nv_bfloat16 bf16;

#define WSZ (512*512)
#define XSZ (8*512*512)
#define FLAGWIN 5e-4f   // ~50x split-GEMM noise in bn units

// ---------------- device scratch ----------------
__device__ bf16     g_wsp[4][2][WSZ];   // weight splits (2 levels, GEMM)
__device__ bf16     g_xT[3][XSZ];       // x^T splits [b][n][c]; 0,1 GEMM; 0+1+2 == exact fp32
__device__ bf16     g_yT[3][XSZ];       // y^T splits
__device__ uint8_t  g_q[XSZ], g_k[XSZ], g_v[XSZ];
__device__ bf16     g_sT[XSZ];          // attn spikes^T bf16 [b][n][c]

// ---------------- PTX helpers (arch-generic, sm_80+) ----------------
__device__ __forceinline__ uint32_t smem_u32(const void* p) {
    uint32_t a;
    asm("{ .reg .u64 t; cvta.to.shared.u64 t, %1; cvt.u32.u64 %0, t; }" : "=r"(a) : "l"(p));
    return a;
}
__device__ __forceinline__ void cp16(uint32_t dst, const void* src) {
    asm volatile("cp.async.cg.shared.global [%0], [%1], 16;" :: "r"(dst), "l"(src) : "memory");
}
__device__ __forceinline__ void cp_commit() { asm volatile("cp.async.commit_group;" ::: "memory"); }
template<int N> __device__ __forceinline__ void cp_wait() {
    asm volatile("cp.async.wait_group %0;" :: "n"(N) : "memory");
}
__device__ __forceinline__ void ldmx4(uint32_t& r0, uint32_t& r1, uint32_t& r2, uint32_t& r3, uint32_t a) {
    asm volatile("ldmatrix.sync.aligned.m8n8.x4.shared.b16 {%0,%1,%2,%3}, [%4];"
                 : "=r"(r0), "=r"(r1), "=r"(r2), "=r"(r3) : "r"(a));
}
__device__ __forceinline__ void mma_bf16(float& c0, float& c1, float& c2, float& c3,
                                         uint32_t a0, uint32_t a1, uint32_t a2, uint32_t a3,
                                         uint32_t b0, uint32_t b1) {
    asm volatile("mma.sync.aligned.m16n8k16.row.col.f32.bf16.bf16.f32 "
                 "{%0,%1,%2,%3}, {%4,%5,%6,%7}, {%8,%9}, {%0,%1,%2,%3};"
                 : "+f"(c0), "+f"(c1), "+f"(c2), "+f"(c3)
                 : "r"(a0), "r"(a1), "r"(a2), "r"(a3), "r"(b0), "r"(b1));
}

// splits (truncation)
__device__ __forceinline__ void split2(float w, bf16& h, bf16& l) {
    h = __float2bfloat16_rz(w);
    l = __float2bfloat16_rz(w - __bfloat162float(h));
}
__device__ __forceinline__ void split3(float w, bf16& h, bf16& l, bf16& ll) {
    h = __float2bfloat16_rz(w);
    float f1 = w - __bfloat162float(h);
    l = __float2bfloat16_rz(f1);
    float f2 = f1 - __bfloat162float(l);
    ll = __float2bfloat16_rz(f2);
}

// ---------------- prep kernels ----------------
__global__ void prep_split4(const float* __restrict__ w0, const float* __restrict__ w1,
                            const float* __restrict__ w2, const float* __restrict__ w3,
                            bf16* __restrict__ dst) {
    const float* ws[4] = {w0, w1, w2, w3};
    const int wi = blockIdx.y;
    const float* w = ws[wi];
    bf16* h = dst + (size_t)(wi * 2 + 0) * WSZ;
    bf16* l = dst + (size_t)(wi * 2 + 1) * WSZ;
    for (int i = blockIdx.x * 256 + threadIdx.x; i < WSZ; i += gridDim.x * 256) {
        bf16 a, b;
        split2(w[i], a, b);
        h[i] = a; l[i] = b;
    }
}

// transpose [b][c][n] -> [b][n][c] with exact 3-way split; z<8: x->xT, z>=8: y->yT
__global__ void prep_xyT(const float* __restrict__ x, const float* __restrict__ y,
                         bf16* __restrict__ xT, bf16* __restrict__ yT) {
    __shared__ float t[32][33];
    const int z = blockIdx.z;
    const int b = z & 7;
    const float* src0 = (z < 8) ? x : y;
    bf16* d0 = (z < 8) ? xT : yT;
    const int c0 = blockIdx.y * 32, n0 = blockIdx.x * 32;
    const int r = threadIdx.x >> 5, j = threadIdx.x & 31;
    const float* src = src0 + ((size_t)b * 512 + c0) * 512 + n0;
#pragma unroll
    for (int i = r; i < 32; i += 8) t[i][j] = src[(size_t)i * 512 + j];
    __syncthreads();
    const size_t dst = ((size_t)b * 512 + n0) * 512 + c0;
#pragma unroll
    for (int i = r; i < 32; i += 8) {
        bf16 a, bb, c;
        split3(t[j][i], a, bb, c);
        d0[0 * (size_t)XSZ + dst + (size_t)i * 512 + j] = a;
        d0[1 * (size_t)XSZ + dst + (size_t)i * 512 + j] = bb;
        d0[2 * (size_t)XSZ + dst + (size_t)i * 512 + j] = c;
    }
}

// ---------------- bf16 mma GEMM + BN + LIF + block-local exact fixup ----------------
// D = A0*B0 + A0*B1 + A1*B0 (NB=2)  or  A0*B0 + A1*B0 (NB=1)
// 128x128 tile, BK=64, 8 stages, double-buffered cp.async, 256 threads (2x4 warps).
// Borderline results queued in smem; drained once per block with exact fp64 dots.
template<int NB, bool OUT_U8>
__device__ __forceinline__ void gemm_body(const bf16* __restrict__ A0, const bf16* __restrict__ A1,
                                          const bf16* __restrict__ B0, const bf16* __restrict__ B1,
                                          void* Out,
                                          const float* __restrict__ gam, const float* __restrict__ bet,
                                          const float* __restrict__ mean, const float* __restrict__ var,
                                          const float* __restrict__ Wexact,   // original fp32 weights
                                          const bf16* __restrict__ Bexact,    // exact-B base (3-level or bf16-exact)
                                          int bz, char* sm) {
    __shared__ int      s_cnt;
    __shared__ uint32_t s_q[256];
    __shared__ double   s_red[8];

    const int NT = 2 + NB;                 // tiles per stage
    const int tid = threadIdx.x;
    const int lane = tid & 31, wid = tid >> 5;
    const int warp_m = wid & 1, warp_n = wid >> 1;
    const int row0 = blockIdx.y * 128, col0 = blockIdx.x * 128;
    const uint32_t sbase = smem_u32(sm);

    if (tid == 0) s_cnt = 0;

    float acc[4][4][4];
#pragma unroll
    for (int i = 0; i < 4; i++)
#pragma unroll
        for (int j = 0; j < 4; j++)
#pragma unroll
            for (int q = 0; q < 4; q++) acc[i][j][q] = 0.0f;

    const bf16* srcs[4];
    srcs[0] = A0 + (size_t)row0 * 512;
    srcs[1] = A1 + (size_t)row0 * 512;
    srcs[2] = B0 + ((size_t)bz * 512 + col0) * 512;
    if (NB == 2) srcs[3] = B1 + ((size_t)bz * 512 + col0) * 512;

    auto issue = [&](int kt, int stg) {
        const uint32_t sb = sbase + stg * NT * 16384;
#pragma unroll
        for (int t = 0; t < NT; t++) {
            const bf16* base = srcs[t] + (kt << 6);
#pragma unroll
            for (int i = 0; i < 4; i++) {
                const int idx = tid + i * 256;
                const int r = idx >> 3, c = idx & 7;
                const uint32_t off = r * 128 + ((c ^ (r & 7)) << 4);
                cp16(sb + t * 16384 + off, base + (size_t)r * 512 + c * 8);
            }
        }
        cp_commit();
    };

    auto ldA = [&](uint32_t Af[4][4], uint32_t sA, int ks) {
#pragma unroll
        for (int tm = 0; tm < 4; tm++) {
            const int r = warp_m * 64 + tm * 16 + (lane & 15);
            const int ch = ks * 2 + (lane >> 4);
            ldmx4(Af[tm][0], Af[tm][1], Af[tm][2], Af[tm][3],
                  sA + r * 128 + ((ch ^ (r & 7)) << 4));
        }
    };
    auto ldB = [&](uint32_t Bf[2][4], uint32_t sB, int ks) {
#pragma unroll
        for (int tp = 0; tp < 2; tp++) {
            const int r = warp_n * 32 + tp * 16 + (lane & 7) + ((lane & 16) >> 1);
            const int ch = ks * 2 + ((lane >> 3) & 1);
            ldmx4(Bf[tp][0], Bf[tp][1], Bf[tp][2], Bf[tp][3],
                  sB + r * 128 + ((ch ^ (r & 7)) << 4));
        }
    };
    auto pass = [&](uint32_t Af[4][4], uint32_t Bf[2][4]) {
#pragma unroll
        for (int tm = 0; tm < 4; tm++)
#pragma unroll
            for (int tn = 0; tn < 4; tn++)
                mma_bf16(acc[tm][tn][0], acc[tm][tn][1], acc[tm][tn][2], acc[tm][tn][3],
                         Af[tm][0], Af[tm][1], Af[tm][2], Af[tm][3],
                         Bf[tn >> 1][(tn & 1) * 2], Bf[tn >> 1][(tn & 1) * 2 + 1]);
    };

    auto compute = [&](int stg) {
        const uint32_t sb = sbase + stg * NT * 16384;
#pragma unroll
        for (int ks = 0; ks < 4; ks++) {
            uint32_t Af0[4][4], Af1[4][4], Bf0[2][4];
            ldA(Af0, sb, ks);
            ldB(Bf0, sb + 2 * 16384, ks);
            ldA(Af1, sb + 16384, ks);
            if (NB == 2) {
                uint32_t Bf1[2][4];
                ldB(Bf1, sb + 3 * 16384, ks);
                pass(Af0, Bf0);
                pass(Af0, Bf1);
                pass(Af1, Bf0);
            } else {
                pass(Af0, Bf0);
                pass(Af1, Bf0);
            }
        }
    };

    issue(0, 0);
    for (int kt = 0; kt < 8; kt++) {
        if (kt + 1 < 8) { issue(kt + 1, (kt + 1) & 1); cp_wait<1>(); }
        else cp_wait<0>();
        __syncthreads();
        compute(kt & 1);
        __syncthreads();
    }

    // ---- epilogue: BN + LIF; flag borderline values into block-local queue ----
    const int r0l = lane >> 2, c0l = (lane & 3) * 2;
#pragma unroll
    for (int tm = 0; tm < 4; tm++) {
#pragma unroll
        for (int half = 0; half < 2; half++) {
            const int m = row0 + warp_m * 64 + tm * 16 + r0l + half * 8;
            const float invv = gam[m] / sqrtf(var[m] + 1e-5f);
            const float offv = bet[m] - mean[m] * invv;
            const size_t rowbase = ((size_t)bz * 512 + m) * 512 + col0 + warp_n * 32;
#pragma unroll
            for (int tn = 0; tn < 4; tn++) {
                const float bn0 = acc[tm][tn][half * 2 + 0] * invv + offv;
                const float bn1 = acc[tm][tn][half * 2 + 1] * invv + offv;
                const bool s0 = (bn0 >= 2.0f);
                const bool s1 = (bn1 >= 2.0f);
                const int ncol = col0 + warp_n * 32 + tn * 8 + c0l;
                if (fabsf(bn0 - 2.0f) < FLAGWIN) {
                    int ix = atomicAdd(&s_cnt, 1);
                    if (ix < 256) s_q[ix] = (uint32_t)m | ((uint32_t)ncol << 16);
                }
                if (fabsf(bn1 - 2.0f) < FLAGWIN) {
                    int ix = atomicAdd(&s_cnt, 1);
                    if (ix < 256) s_q[ix] = (uint32_t)m | ((uint32_t)(ncol + 1) << 16);
                }
                const size_t o = rowbase + tn * 8 + c0l;
                if (OUT_U8) {
                    *(unsigned short*)((uint8_t*)Out + o) =
                        (unsigned short)((s0 ? 1u : 0u) | ((s1 ? 1u : 0u) << 8));
                } else {
                    *(float2*)((float*)Out + o) = make_float2(s0 ? 1.f : 0.f, s1 ? 1.f : 0.f);
                }
            }
        }
    }

    // ---- drain block-local fixup queue (usually empty): exact fp64 recompute ----
    __syncthreads();
    const int fcnt = (s_cnt < 256) ? s_cnt : 256;
    for (int e = 0; e < fcnt; e++) {
        const uint32_t qe = s_q[e];
        const int fm = (int)(qe & 0xffffu);
        const int fn = (int)(qe >> 16);
        const float* Wr = Wexact + (size_t)fm * 512;
        const bf16* Br = Bexact + ((size_t)bz * 512 + fn) * 512;
        double s = 0.0;
#pragma unroll
        for (int rr = 0; rr < 2; rr++) {
            const int c = tid + rr * 256;
            double xv;
            if (NB == 2) {
                xv = (double)__bfloat162float(Br[c]) +
                     (double)__bfloat162float(Br[(size_t)XSZ + c]) +
                     (double)__bfloat162float(Br[2 * (size_t)XSZ + c]);   // exact fp32 value
            } else {
                xv = (double)__bfloat162float(Br[c]);                     // spikes exact in bf16
            }
            s += (double)Wr[c] * xv;
        }
#pragma unroll
        for (int o = 16; o; o >>= 1) s += __shfl_down_sync(0xffffffffu, s, o);
        if (lane == 0) s_red[wid] = s;
        __syncthreads();
        if (tid == 0) {
            double sum = s_red[0];
#pragma unroll
            for (int i = 1; i < 8; i++) sum += s_red[i];
            const double inv = (double)gam[fm] / sqrt((double)var[fm] + 1e-5);
            const double bne = sum * inv + ((double)bet[fm] - (double)mean[fm] * inv);
            const size_t o = ((size_t)bz * 512 + fm) * 512 + fn;
            if (OUT_U8) ((uint8_t*)Out)[o] = (bne >= 2.0) ? (uint8_t)1 : (uint8_t)0;
            else        ((float*)Out)[o]   = (bne >= 2.0) ? 1.0f : 0.0f;
        }
        __syncthreads();
    }
}

struct QKVp {
    const bf16 *A0[3], *A1[3], *B0[3], *B1[3];
    const float* Wx[3];        // original fp32 weights for exact fixup
    const bf16* Bx[3];         // exact-B base (3-level xT/yT)
    uint8_t* out[3];
    const float *gam[3], *bet[3], *mean[3], *var[3];
};

__global__ __launch_bounds__(256, 1) void gemm_qkv(QKVp P) {
    extern __shared__ char sm[];
    const int which = blockIdx.z >> 3;
    const int bz = blockIdx.z & 7;
    gemm_body<2, true>(P.A0[which], P.A1[which], P.B0[which], P.B1[which], P.out[which],
                       P.gam[which], P.bet[which], P.mean[which], P.var[which],
                       P.Wx[which], P.Bx[which], bz, sm);
}

__global__ __launch_bounds__(256, 1) void gemm_proj(const bf16* A0, const bf16* A1,
                                                    const bf16* B0, float* Out,
                                                    const float* g, const float* b,
                                                    const float* m, const float* v,
                                                    const float* Wx) {
    extern __shared__ char sm[];
    gemm_body<1, false>(A0, A1, B0, B0, Out, g, b, m, v, Wx, B0, blockIdx.z, sm);
}

// ---------------- spiking attention: o = Q (K^T V), exact int math ----------------
__global__ __launch_bounds__(512)
void attn_lif(const uint8_t* __restrict__ q, const uint8_t* __restrict__ k,
              const uint8_t* __restrict__ v, bf16* __restrict__ sT) {
    __shared__ uint32_t ks[32 * 133];
    __shared__ uint32_t vs[32 * 133];
    __shared__ int M[32][33];

    const int tid = threadIdx.x;
    const int tb = blockIdx.x >> 4;
    const int h = blockIdx.x & 15;
    const size_t base = ((size_t)tb * 512 + h * 32) * 512;

    const uint32_t* ksrc = (const uint32_t*)(k + base);
    const uint32_t* vsrc = (const uint32_t*)(v + base);
    for (int f = tid; f < 2 * 4096; f += 512) {
        const int r = (f >> 7) & 31, w = f & 127;
        if (f < 4096) ks[r * 133 + w] = ksrc[r * 128 + w];
        else          vs[r * 133 + w] = vsrc[r * 128 + w];
    }
    __syncthreads();

    if (tid < 256) {
        const int dp = tid >> 3, dd0 = (tid & 7) * 4;
        unsigned a0 = 0, a1 = 0, a2 = 0, a3 = 0;
        const uint32_t* kr = &ks[dp * 133];
        const uint32_t* v0 = &vs[(dd0 + 0) * 133];
        const uint32_t* v1 = &vs[(dd0 + 1) * 133];
        const uint32_t* v2 = &vs[(dd0 + 2) * 133];
        const uint32_t* v3 = &vs[(dd0 + 3) * 133];
#pragma unroll 8
        for (int w = 0; w < 128; w++) {
            const uint32_t kw = kr[w];
            a0 = __dp4a(kw, v0[w], a0);
            a1 = __dp4a(kw, v1[w], a1);
            a2 = __dp4a(kw, v2[w], a2);
            a3 = __dp4a(kw, v3[w], a3);
        }
        M[dp][dd0 + 0] = (int)a0; M[dp][dd0 + 1] = (int)a1;
        M[dp][dd0 + 2] = (int)a2; M[dp][dd0 + 3] = (int)a3;
    }
    __syncthreads();

    const int n = tid;
    int oacc[32];
#pragma unroll
    for (int d = 0; d < 32; d++) oacc[d] = 0;
#pragma unroll 4
    for (int dp = 0; dp < 32; dp++) {
        if (q[base + (size_t)dp * 512 + n]) {
#pragma unroll
            for (int d = 0; d < 32; d++) oacc[d] += M[dp][d];
        }
    }
    // LIF(o*0.25/2) == (o_int >= 8). Write spikes^T as bf16 {0,1} at [b][n][c].
    uint32_t* dst = (uint32_t*)(sT + ((size_t)tb * 512 + n) * 512 + h * 32);
#pragma unroll
    for (int g = 0; g < 16; g++) {
        const uint32_t lo = (oacc[2 * g] >= 8) ? 0x3F80u : 0u;
        const uint32_t hi = (oacc[2 * g + 1] >= 8) ? 0x3F80u : 0u;
        dst[g] = lo | (hi << 16);
    }
}

// ---------------------------------------------------------------------------
extern "C" void kernel_launch(void* const* d_in, const int* in_sizes, int n_in,
                              void* d_out, int out_size) {
    (void)in_sizes; (void)n_in; (void)out_size;
    const float* x = (const float*)d_in[0];
    const float* y = (const float*)d_in[1];
    const float* w[4]  = {(const float*)d_in[2], (const float*)d_in[7], (const float*)d_in[12], (const float*)d_in[17]};
    const float* bg[4] = {(const float*)d_in[3], (const float*)d_in[8], (const float*)d_in[13], (const float*)d_in[18]};
    const float* bb[4] = {(const float*)d_in[4], (const float*)d_in[9], (const float*)d_in[14], (const float*)d_in[19]};
    const float* bm[4] = {(const float*)d_in[5], (const float*)d_in[10], (const float*)d_in[15], (const float*)d_in[20]};
    const float* bv[4] = {(const float*)d_in[6], (const float*)d_in[11], (const float*)d_in[16], (const float*)d_in[21]};

    bf16 *wsp, *xT, *yT, *sT;
    uint8_t *gq, *gk, *gv;
    cudaGetSymbolAddress((void**)&wsp, g_wsp);
    cudaGetSymbolAddress((void**)&xT, g_xT);
    cudaGetSymbolAddress((void**)&yT, g_yT);
    cudaGetSymbolAddress((void**)&sT, g_sT);
    cudaGetSymbolAddress((void**)&gq, g_q);
    cudaGetSymbolAddress((void**)&gk, g_k);
    cudaGetSymbolAddress((void**)&gv, g_v);

    cudaFuncSetAttribute(gemm_qkv, cudaFuncAttributeMaxDynamicSharedMemorySize, 131072);
    cudaFuncSetAttribute(gemm_proj, cudaFuncAttributeMaxDynamicSharedMemorySize, 98304);

    prep_split4<<<dim3(64, 4), 256>>>(w[0], w[1], w[2], w[3], wsp);
    prep_xyT<<<dim3(16, 16, 16), 256>>>(x, y, xT, yT);

    QKVp P;
    uint8_t* outs[3] = {gq, gk, gv};
    for (int g = 0; g < 3; g++) {
        P.A0[g] = wsp + (size_t)(g * 2 + 0) * WSZ;
        P.A1[g] = wsp + (size_t)(g * 2 + 1) * WSZ;
        P.B0[g] = (g == 0) ? xT : yT;
        P.B1[g] = ((g == 0) ? xT : yT) + (size_t)XSZ;
        P.Wx[g] = w[g];
        P.Bx[g] = (g == 0) ? xT : yT;
        P.out[g] = outs[g];
        P.gam[g] = bg[g]; P.bet[g] = bb[g]; P.mean[g] = bm[g]; P.var[g] = bv[g];
    }
    gemm_qkv<<<dim3(4, 4, 24), 256, 131072>>>(P);

    attn_lif<<<128, 512>>>(gq, gk, gv, sT);

    gemm_proj<<<dim3(4, 4, 8), 256, 98304>>>(wsp + 6 * (size_t)WSZ, wsp + 7 * (size_t)WSZ,
                                             sT, (float*)d_out, bg[3], bb[3], bm[3], bv[3], w[3]);
}

// round 15
// speedup vs baseline: 1.4781x; 1.4781x over previous
#include <cuda_runtime.h>
#include <cuda_bf16.h>
#include <cstdint>

typedef __nv_bfloat16 bf16;

#define WSZ (512*512)
#define XSZ (8*512*512)
#define FIXCAP (1<<20)
#define FLAGWIN 5e-4f   // ~50x split-GEMM noise in bn units

// ---------------- device scratch ----------------
__device__ bf16     g_wsp[4][2][WSZ];   // weight splits (2 levels)
__device__ bf16     g_xT[2][XSZ];       // x^T splits [b][n][c]
__device__ bf16     g_yT[2][XSZ];       // y^T splits
__device__ uint8_t  g_q[XSZ], g_k[XSZ], g_v[XSZ];
__device__ bf16     g_sT[XSZ];          // attn spikes^T bf16 [b][n][c]
__device__ int      g_cnt[2];
__device__ uint32_t g_fix[2][FIXCAP];

// ---------------- PTX helpers (arch-generic, sm_80+) ----------------
__device__ __forceinline__ uint32_t smem_u32(const void* p) {
    uint32_t a;
    asm("{ .reg .u64 t; cvta.to.shared.u64 t, %1; cvt.u32.u64 %0, t; }" : "=r"(a) : "l"(p));
    return a;
}
__device__ __forceinline__ void cp16(uint32_t dst, const void* src) {
    asm volatile("cp.async.cg.shared.global [%0], [%1], 16;" :: "r"(dst), "l"(src) : "memory");
}
__device__ __forceinline__ void cp_commit() { asm volatile("cp.async.commit_group;" ::: "memory"); }
template<int N> __device__ __forceinline__ void cp_wait() {
    asm volatile("cp.async.wait_group %0;" :: "n"(N) : "memory");
}
__device__ __forceinline__ void ldmx4(uint32_t& r0, uint32_t& r1, uint32_t& r2, uint32_t& r3, uint32_t a) {
    asm volatile("ldmatrix.sync.aligned.m8n8.x4.shared.b16 {%0,%1,%2,%3}, [%4];"
                 : "=r"(r0), "=r"(r1), "=r"(r2), "=r"(r3) : "r"(a));
}
__device__ __forceinline__ void mma_bf16(float& c0, float& c1, float& c2, float& c3,
                                         uint32_t a0, uint32_t a1, uint32_t a2, uint32_t a3,
                                         uint32_t b0, uint32_t b1) {
    asm volatile("mma.sync.aligned.m16n8k16.row.col.f32.bf16.bf16.f32 "
                 "{%0,%1,%2,%3}, {%4,%5,%6,%7}, {%8,%9}, {%0,%1,%2,%3};"
                 : "+f"(c0), "+f"(c1), "+f"(c2), "+f"(c3)
                 : "r"(a0), "r"(a1), "r"(a2), "r"(a3), "r"(b0), "r"(b1));
}

// 2-way bf16 split (truncation): w ≈ h + l, residual ~2^-16 relative
__device__ __forceinline__ void split2(float w, bf16& h, bf16& l) {
    h = __float2bfloat16_rz(w);
    l = __float2bfloat16_rz(w - __bfloat162float(h));
}

// ---------------- prep kernels ----------------
__global__ void prep_split4(const float* __restrict__ w0, const float* __restrict__ w1,
                            const float* __restrict__ w2, const float* __restrict__ w3,
                            bf16* __restrict__ dst) {
    if (blockIdx.x == 0 && blockIdx.y == 0 && threadIdx.x == 0) { g_cnt[0] = 0; g_cnt[1] = 0; }
    const float* ws[4] = {w0, w1, w2, w3};
    const int wi = blockIdx.y;
    const float* w = ws[wi];
    bf16* h = dst + (size_t)(wi * 2 + 0) * WSZ;
    bf16* l = dst + (size_t)(wi * 2 + 1) * WSZ;
    for (int i = blockIdx.x * 256 + threadIdx.x; i < WSZ; i += gridDim.x * 256) {
        bf16 a, b;
        split2(w[i], a, b);
        h[i] = a; l[i] = b;
    }
}

// transpose [b][c][n] -> [b][n][c] with 2-way split; z<8: x->xT, z>=8: y->yT
__global__ void prep_xyT(const float* __restrict__ x, const float* __restrict__ y,
                         bf16* __restrict__ xT, bf16* __restrict__ yT) {
    __shared__ float t[32][33];
    const int z = blockIdx.z;
    const int b = z & 7;
    const float* src0 = (z < 8) ? x : y;
    bf16* d0 = (z < 8) ? xT : yT;
    const int c0 = blockIdx.y * 32, n0 = blockIdx.x * 32;
    const int r = threadIdx.x >> 5, j = threadIdx.x & 31;
    const float* src = src0 + ((size_t)b * 512 + c0) * 512 + n0;
#pragma unroll
    for (int i = r; i < 32; i += 8) t[i][j] = src[(size_t)i * 512 + j];
    __syncthreads();
    const size_t dst = ((size_t)b * 512 + n0) * 512 + c0;
#pragma unroll
    for (int i = r; i < 32; i += 8) {
        bf16 a, bb;
        split2(t[j][i], a, bb);
        d0[0 * (size_t)XSZ + dst + (size_t)i * 512 + j] = a;
        d0[1 * (size_t)XSZ + dst + (size_t)i * 512 + j] = bb;
    }
}

// ---------------- bf16 mma GEMM + BN + LIF (+ borderline flagging) ----------------
// D = A0*B0 + A0*B1 + A1*B0 (NB=2)  or  A0*B0 + A1*B0 (NB=1)
// 128x128 tile, BK=64, 8 stages, double-buffered cp.async, 256 threads (2x4 warps).
template<int NB, bool OUT_U8>
__device__ __forceinline__ void gemm_body(const bf16* __restrict__ A0, const bf16* __restrict__ A1,
                                          const bf16* __restrict__ B0, const bf16* __restrict__ B1,
                                          void* Out,
                                          const float* __restrict__ gam, const float* __restrict__ bet,
                                          const float* __restrict__ mean, const float* __restrict__ var,
                                          int bz, int stage, int which, char* sm) {
    const int NT = 2 + NB;                 // tiles per stage
    const int tid = threadIdx.x;
    const int lane = tid & 31, wid = tid >> 5;
    const int warp_m = wid & 1, warp_n = wid >> 1;
    const int row0 = blockIdx.y * 128, col0 = blockIdx.x * 128;
    const uint32_t sbase = smem_u32(sm);

    float acc[4][4][4];
#pragma unroll
    for (int i = 0; i < 4; i++)
#pragma unroll
        for (int j = 0; j < 4; j++)
#pragma unroll
            for (int q = 0; q < 4; q++) acc[i][j][q] = 0.0f;

    const bf16* srcs[4];
    srcs[0] = A0 + (size_t)row0 * 512;
    srcs[1] = A1 + (size_t)row0 * 512;
    srcs[2] = B0 + ((size_t)bz * 512 + col0) * 512;
    if (NB == 2) srcs[3] = B1 + ((size_t)bz * 512 + col0) * 512;

    // stage = NT tiles of [128][64] bf16; tile chunk (r, c): 16B at row r, chunk c^(r&7)
    auto issue = [&](int kt, int stg) {
        const uint32_t sb = sbase + stg * NT * 16384;
#pragma unroll
        for (int t = 0; t < NT; t++) {
            const bf16* base = srcs[t] + (kt << 6);
#pragma unroll
            for (int i = 0; i < 4; i++) {
                const int idx = tid + i * 256;
                const int r = idx >> 3, c = idx & 7;
                const uint32_t off = r * 128 + ((c ^ (r & 7)) << 4);
                cp16(sb + t * 16384 + off, base + (size_t)r * 512 + c * 8);
            }
        }
        cp_commit();
    };

    auto ldA = [&](uint32_t Af[4][4], uint32_t sA, int ks) {
#pragma unroll
        for (int tm = 0; tm < 4; tm++) {
            const int r = warp_m * 64 + tm * 16 + (lane & 15);
            const int ch = ks * 2 + (lane >> 4);
            ldmx4(Af[tm][0], Af[tm][1], Af[tm][2], Af[tm][3],
                  sA + r * 128 + ((ch ^ (r & 7)) << 4));
        }
    };
    auto ldB = [&](uint32_t Bf[2][4], uint32_t sB, int ks) {
#pragma unroll
        for (int tp = 0; tp < 2; tp++) {
            const int r = warp_n * 32 + tp * 16 + (lane & 7) + ((lane & 16) >> 1);
            const int ch = ks * 2 + ((lane >> 3) & 1);
            ldmx4(Bf[tp][0], Bf[tp][1], Bf[tp][2], Bf[tp][3],
                  sB + r * 128 + ((ch ^ (r & 7)) << 4));
        }
    };
    auto pass = [&](uint32_t Af[4][4], uint32_t Bf[2][4]) {
#pragma unroll
        for (int tm = 0; tm < 4; tm++)
#pragma unroll
            for (int tn = 0; tn < 4; tn++)
                mma_bf16(acc[tm][tn][0], acc[tm][tn][1], acc[tm][tn][2], acc[tm][tn][3],
                         Af[tm][0], Af[tm][1], Af[tm][2], Af[tm][3],
                         Bf[tn >> 1][(tn & 1) * 2], Bf[tn >> 1][(tn & 1) * 2 + 1]);
    };

    auto compute = [&](int stg) {
        const uint32_t sb = sbase + stg * NT * 16384;
#pragma unroll
        for (int ks = 0; ks < 4; ks++) {
            uint32_t Af0[4][4], Af1[4][4], Bf0[2][4];
            ldA(Af0, sb, ks);
            ldB(Bf0, sb + 2 * 16384, ks);
            ldA(Af1, sb + 16384, ks);
            if (NB == 2) {
                uint32_t Bf1[2][4];
                ldB(Bf1, sb + 3 * 16384, ks);
                pass(Af0, Bf0);
                pass(Af0, Bf1);
                pass(Af1, Bf0);
            } else {
                pass(Af0, Bf0);
                pass(Af1, Bf0);
            }
        }
    };

    issue(0, 0);
    for (int kt = 0; kt < 8; kt++) {
        if (kt + 1 < 8) { issue(kt + 1, (kt + 1) & 1); cp_wait<1>(); }
        else cp_wait<0>();
        __syncthreads();
        compute(kt & 1);
        __syncthreads();
    }

    // ---- epilogue: BN + LIF; flag borderline values for exact fp64 fixup ----
    const int r0l = lane >> 2, c0l = (lane & 3) * 2;
#pragma unroll
    for (int tm = 0; tm < 4; tm++) {
#pragma unroll
        for (int half = 0; half < 2; half++) {
            const int m = row0 + warp_m * 64 + tm * 16 + r0l + half * 8;
            const float invv = gam[m] / sqrtf(var[m] + 1e-5f);
            const float offv = bet[m] - mean[m] * invv;
            const size_t rowbase = ((size_t)bz * 512 + m) * 512 + col0 + warp_n * 32;
#pragma unroll
            for (int tn = 0; tn < 4; tn++) {
                const float bn0 = acc[tm][tn][half * 2 + 0] * invv + offv;
                const float bn1 = acc[tm][tn][half * 2 + 1] * invv + offv;
                const bool s0 = (bn0 >= 2.0f);
                const bool s1 = (bn1 >= 2.0f);
                const int ncol = col0 + warp_n * 32 + tn * 8 + c0l;
                if (fabsf(bn0 - 2.0f) < FLAGWIN) {
                    int ix = atomicAdd(&g_cnt[stage], 1);
                    if (ix < FIXCAP)
                        g_fix[stage][ix] = (uint32_t)which | ((uint32_t)bz << 2) |
                                           ((uint32_t)m << 5) | ((uint32_t)ncol << 14);
                }
                if (fabsf(bn1 - 2.0f) < FLAGWIN) {
                    int ix = atomicAdd(&g_cnt[stage], 1);
                    if (ix < FIXCAP)
                        g_fix[stage][ix] = (uint32_t)which | ((uint32_t)bz << 2) |
                                           ((uint32_t)m << 5) | ((uint32_t)(ncol + 1) << 14);
                }
                const size_t o = rowbase + tn * 8 + c0l;
                if (OUT_U8) {
                    *(unsigned short*)((uint8_t*)Out + o) =
                        (unsigned short)((s0 ? 1u : 0u) | ((s1 ? 1u : 0u) << 8));
                } else {
                    *(float2*)((float*)Out + o) = make_float2(s0 ? 1.f : 0.f, s1 ? 1.f : 0.f);
                }
            }
        }
    }
}

struct QKVp {
    const bf16 *A0[3], *A1[3], *B0[3], *B1[3];
    uint8_t* out[3];
    const float *gam[3], *bet[3], *mean[3], *var[3];
};

__global__ __launch_bounds__(256, 1) void gemm_qkv(QKVp P) {
    extern __shared__ char sm[];
    const int which = blockIdx.z >> 3;
    const int bz = blockIdx.z & 7;
    gemm_body<2, true>(P.A0[which], P.A1[which], P.B0[which], P.B1[which], P.out[which],
                       P.gam[which], P.bet[which], P.mean[which], P.var[which],
                       bz, 0, which, sm);
}

__global__ __launch_bounds__(256, 1) void gemm_proj(const bf16* A0, const bf16* A1,
                                                    const bf16* B0, float* Out,
                                                    const float* g, const float* b,
                                                    const float* m, const float* v) {
    extern __shared__ char sm[];
    gemm_body<1, false>(A0, A1, B0, B0, Out, g, b, m, v, blockIdx.z, 1, 0, sm);
}

// ---------------- exact fp64 fixup of borderline spikes ----------------
// ONE BLOCK PER ENTRY: 256 threads x 2 channels -> one memory round + 2-level reduce.
struct FixQ {
    const float* in[3];    // original [b][c][n]
    const float* w[3];
    const float *g[3], *be[3], *mn[3], *vr[3];
    uint8_t* out[3];
};

__global__ __launch_bounds__(256) void fixup_qkv(FixQ P) {
    __shared__ double red[8];
    const int cnt0 = g_cnt[0];
    const int cnt = cnt0 < FIXCAP ? cnt0 : FIXCAP;
    const int tid = threadIdx.x, lane = tid & 31, wid = tid >> 5;
    for (int e = blockIdx.x; e < cnt; e += gridDim.x) {
        const uint32_t t = g_fix[0][e];
        const int which = t & 3, b = (t >> 2) & 7, m = (t >> 5) & 511, n = (t >> 14) & 511;
        const float* W = P.w[which] + (size_t)m * 512;
        const float* X = P.in[which] + (size_t)b * 262144 + n;
        const float w0 = W[tid],        x0 = X[(size_t)tid * 512];
        const float w1 = W[tid + 256],  x1 = X[(size_t)(tid + 256) * 512];
        double s = (double)w0 * (double)x0 + (double)w1 * (double)x1;
#pragma unroll
        for (int o = 16; o; o >>= 1) s += __shfl_down_sync(0xffffffffu, s, o);
        if (lane == 0) red[wid] = s;
        __syncthreads();
        if (tid == 0) {
            double sum = red[0];
#pragma unroll
            for (int i = 1; i < 8; i++) sum += red[i];
            const double inv = (double)P.g[which][m] / sqrt((double)P.vr[which][m] + 1e-5);
            const double bn = sum * inv + ((double)P.be[which][m] - (double)P.mn[which][m] * inv);
            P.out[which][((size_t)b * 512 + m) * 512 + n] = (bn >= 2.0) ? (uint8_t)1 : (uint8_t)0;
        }
        __syncthreads();
    }
}

__global__ __launch_bounds__(256) void fixup_proj(const float* __restrict__ pw,
                                                  const bf16* __restrict__ sT, float* __restrict__ out,
                                                  const float* __restrict__ g, const float* __restrict__ be,
                                                  const float* __restrict__ mn, const float* __restrict__ vr) {
    __shared__ double red[8];
    const int cnt0 = g_cnt[1];
    const int cnt = cnt0 < FIXCAP ? cnt0 : FIXCAP;
    const int tid = threadIdx.x, lane = tid & 31, wid = tid >> 5;
    for (int e = blockIdx.x; e < cnt; e += gridDim.x) {
        const uint32_t t = g_fix[1][e];
        const int b = (t >> 2) & 7, m = (t >> 5) & 511, n = (t >> 14) & 511;
        const float* W = pw + (size_t)m * 512;
        const bf16* S = sT + ((size_t)b * 512 + n) * 512;
        const float w0 = W[tid],       x0 = __bfloat162float(S[tid]);
        const float w1 = W[tid + 256], x1 = __bfloat162float(S[tid + 256]);
        double s = (double)w0 * (double)x0 + (double)w1 * (double)x1;
#pragma unroll
        for (int o = 16; o; o >>= 1) s += __shfl_down_sync(0xffffffffu, s, o);
        if (lane == 0) red[wid] = s;
        __syncthreads();
        if (tid == 0) {
            double sum = red[0];
#pragma unroll
            for (int i = 1; i < 8; i++) sum += red[i];
            const double inv = (double)g[m] / sqrt((double)vr[m] + 1e-5);
            const double bn = sum * inv + ((double)be[m] - (double)mn[m] * inv);
            out[((size_t)b * 512 + m) * 512 + n] = (bn >= 2.0) ? 1.0f : 0.0f;
        }
        __syncthreads();
    }
}

// ---------------- spiking attention: o = Q (K^T V), bit-packed popc, exact ----------------
__global__ __launch_bounds__(512)
void attn_lif(const uint8_t* __restrict__ q, const uint8_t* __restrict__ k,
              const uint8_t* __restrict__ v, bf16* __restrict__ sT) {
    __shared__ uint32_t kb[32][17];   // K spike bits, padded vs bank conflicts
    __shared__ uint32_t vb[32][17];   // V spike bits
    __shared__ int M[32][33];

    const int tid = threadIdx.x;
    const int lane = tid & 31;
    const int tb = blockIdx.x >> 4;
    const int h = blockIdx.x & 15;
    const size_t base = ((size_t)tb * 512 + h * 32) * 512;

    // Pack K, V spike bytes (0/1) into bitmasks via warp ballot: 32 rows x 512 bits.
#pragma unroll
    for (int i = 0; i < 32; i++) {
        const unsigned bk = __ballot_sync(0xffffffffu, k[base + (size_t)i * 512 + tid] != 0);
        const unsigned bv = __ballot_sync(0xffffffffu, v[base + (size_t)i * 512 + tid] != 0);
        if (lane == 0) { kb[i][tid >> 5] = bk; vb[i][tid >> 5] = bv; }
    }
    __syncthreads();

    // M[dp][dd] = popc over 512 bits of (K row dp AND V row dd). 1024 entries, 2 per thread.
#pragma unroll
    for (int e = tid; e < 1024; e += 512) {
        const int dp = e >> 5, dd = e & 31;
        int acc = 0;
#pragma unroll
        for (int w = 0; w < 16; w++)
            acc += __popc(kb[dp][w] & vb[dd][w]);
        M[dp][dd] = acc;
    }
    __syncthreads();

    // o[n][d] = sum_dp q[dp][n] * M[dp][d]; spike = (o_int >= 8) (exact: *0.25/2 binary)
    const int n = tid;
    int oacc[32];
#pragma unroll
    for (int d = 0; d < 32; d++) oacc[d] = 0;
#pragma unroll 4
    for (int dp = 0; dp < 32; dp++) {
        if (q[base + (size_t)dp * 512 + n]) {
#pragma unroll
            for (int d = 0; d < 32; d++) oacc[d] += M[dp][d];
        }
    }
    uint32_t* dst = (uint32_t*)(sT + ((size_t)tb * 512 + n) * 512 + h * 32);
#pragma unroll
    for (int g = 0; g < 16; g++) {
        const uint32_t lo = (oacc[2 * g] >= 8) ? 0x3F80u : 0u;
        const uint32_t hi = (oacc[2 * g + 1] >= 8) ? 0x3F80u : 0u;
        dst[g] = lo | (hi << 16);
    }
}

// ---------------------------------------------------------------------------
extern "C" void kernel_launch(void* const* d_in, const int* in_sizes, int n_in,
                              void* d_out, int out_size) {
    (void)in_sizes; (void)n_in; (void)out_size;
    const float* x = (const float*)d_in[0];
    const float* y = (const float*)d_in[1];
    const float* w[4]  = {(const float*)d_in[2], (const float*)d_in[7], (const float*)d_in[12], (const float*)d_in[17]};
    const float* bg[4] = {(const float*)d_in[3], (const float*)d_in[8], (const float*)d_in[13], (const float*)d_in[18]};
    const float* bb[4] = {(const float*)d_in[4], (const float*)d_in[9], (const float*)d_in[14], (const float*)d_in[19]};
    const float* bm[4] = {(const float*)d_in[5], (const float*)d_in[10], (const float*)d_in[15], (const float*)d_in[20]};
    const float* bv[4] = {(const float*)d_in[6], (const float*)d_in[11], (const float*)d_in[16], (const float*)d_in[21]};

    bf16 *wsp, *xT, *yT, *sT;
    uint8_t *gq, *gk, *gv;
    cudaGetSymbolAddress((void**)&wsp, g_wsp);
    cudaGetSymbolAddress((void**)&xT, g_xT);
    cudaGetSymbolAddress((void**)&yT, g_yT);
    cudaGetSymbolAddress((void**)&sT, g_sT);
    cudaGetSymbolAddress((void**)&gq, g_q);
    cudaGetSymbolAddress((void**)&gk, g_k);
    cudaGetSymbolAddress((void**)&gv, g_v);

    cudaFuncSetAttribute(gemm_qkv, cudaFuncAttributeMaxDynamicSharedMemorySize, 131072);
    cudaFuncSetAttribute(gemm_proj, cudaFuncAttributeMaxDynamicSharedMemorySize, 98304);

    prep_split4<<<dim3(64, 4), 256>>>(w[0], w[1], w[2], w[3], wsp);
    prep_xyT<<<dim3(16, 16, 16), 256>>>(x, y, xT, yT);

    QKVp P;
    uint8_t* outs[3] = {gq, gk, gv};
    for (int g = 0; g < 3; g++) {
        P.A0[g] = wsp + (size_t)(g * 2 + 0) * WSZ;
        P.A1[g] = wsp + (size_t)(g * 2 + 1) * WSZ;
        P.B0[g] = (g == 0) ? xT : yT;
        P.B1[g] = ((g == 0) ? xT : yT) + (size_t)XSZ;
        P.out[g] = outs[g];
        P.gam[g] = bg[g]; P.bet[g] = bb[g]; P.mean[g] = bm[g]; P.var[g] = bv[g];
    }
    gemm_qkv<<<dim3(4, 4, 24), 256, 131072>>>(P);

    FixQ F;
    F.in[0] = x; F.in[1] = y; F.in[2] = y;
    for (int g = 0; g < 3; g++) {
        F.w[g] = w[g]; F.g[g] = bg[g]; F.be[g] = bb[g]; F.mn[g] = bm[g]; F.vr[g] = bv[g];
        F.out[g] = outs[g];
    }
    fixup_qkv<<<1024, 256>>>(F);

    attn_lif<<<128, 512>>>(gq, gk, gv, sT);

    gemm_proj<<<dim3(4, 4, 8), 256, 98304>>>(wsp + 6 * (size_t)WSZ, wsp + 7 * (size_t)WSZ,
                                             sT, (float*)d_out, bg[3], bb[3], bm[3], bv[3]);

    fixup_proj<<<1024, 256>>>(w[3], sT, (float*)d_out, bg[3], bb[3], bm[3], bv[3]);
}

// round 16
// speedup vs baseline: 1.5808x; 1.0694x over previous
#include <cuda_runtime.h>
#include <cuda_bf16.h>
#include <cstdint>

typedef __nv_bfloat16 bf16;

#define WSZ (512*512)
#define XSZ (8*512*512)
#define FIXCAP (1<<20)
#define FLAGWIN 1.5e-4f   // ~25 sigma of split-GEMM noise (sigma ~ 6e-6 in bn units)

// ---------------- device scratch ----------------
__device__ bf16     g_wsp[4][2][WSZ];   // weight splits (2 levels)
__device__ bf16     g_xT[2][XSZ];       // x^T splits [b][n][c]
__device__ bf16     g_yT[2][XSZ];       // y^T splits
__device__ uint8_t  g_q[XSZ], g_k[XSZ], g_v[XSZ];
__device__ bf16     g_sT[XSZ];          // attn spikes^T bf16 [b][n][c]
__device__ int      g_cnt[2];
__device__ uint32_t g_fix[2][FIXCAP];

// ---------------- PTX helpers (arch-generic, sm_80+) ----------------
__device__ __forceinline__ uint32_t smem_u32(const void* p) {
    uint32_t a;
    asm("{ .reg .u64 t; cvta.to.shared.u64 t, %1; cvt.u32.u64 %0, t; }" : "=r"(a) : "l"(p));
    return a;
}
__device__ __forceinline__ void cp16(uint32_t dst, const void* src) {
    asm volatile("cp.async.cg.shared.global [%0], [%1], 16;" :: "r"(dst), "l"(src) : "memory");
}
__device__ __forceinline__ void cp_commit() { asm volatile("cp.async.commit_group;" ::: "memory"); }
template<int N> __device__ __forceinline__ void cp_wait() {
    asm volatile("cp.async.wait_group %0;" :: "n"(N) : "memory");
}
__device__ __forceinline__ void ldmx4(uint32_t& r0, uint32_t& r1, uint32_t& r2, uint32_t& r3, uint32_t a) {
    asm volatile("ldmatrix.sync.aligned.m8n8.x4.shared.b16 {%0,%1,%2,%3}, [%4];"
                 : "=r"(r0), "=r"(r1), "=r"(r2), "=r"(r3) : "r"(a));
}
__device__ __forceinline__ void mma_bf16(float& c0, float& c1, float& c2, float& c3,
                                         uint32_t a0, uint32_t a1, uint32_t a2, uint32_t a3,
                                         uint32_t b0, uint32_t b1) {
    asm volatile("mma.sync.aligned.m16n8k16.row.col.f32.bf16.bf16.f32 "
                 "{%0,%1,%2,%3}, {%4,%5,%6,%7}, {%8,%9}, {%0,%1,%2,%3};"
                 : "+f"(c0), "+f"(c1), "+f"(c2), "+f"(c3)
                 : "r"(a0), "r"(a1), "r"(a2), "r"(a3), "r"(b0), "r"(b1));
}

// 2-way bf16 split (truncation): w ≈ h + l, residual ~2^-16 relative
__device__ __forceinline__ void split2(float w, bf16& h, bf16& l) {
    h = __float2bfloat16_rz(w);
    l = __float2bfloat16_rz(w - __bfloat162float(h));
}

// ---------------- fused prep: weight splits + input transpose/splits ----------------
// blocks [0,256): weight split (4 weights x 64 blocks)
// blocks [256,4352): transpose+split (16x16x16 tiles: x for z<8, y for z>=8)
__global__ void prep_all(const float* __restrict__ x, const float* __restrict__ y,
                         const float* __restrict__ w0, const float* __restrict__ w1,
                         const float* __restrict__ w2, const float* __restrict__ w3,
                         bf16* __restrict__ wsp, bf16* __restrict__ xT, bf16* __restrict__ yT) {
    const int blk = blockIdx.x;
    if (blk < 256) {
        if (blk == 0 && threadIdx.x == 0) { g_cnt[0] = 0; g_cnt[1] = 0; }
        const float* ws[4] = {w0, w1, w2, w3};
        const int wi = blk >> 6;
        const int sub = blk & 63;
        const float* w = ws[wi];
        bf16* h = wsp + (size_t)(wi * 2 + 0) * WSZ;
        bf16* l = wsp + (size_t)(wi * 2 + 1) * WSZ;
        for (int i = sub * 256 + threadIdx.x; i < WSZ; i += 64 * 256) {
            bf16 a, b;
            split2(w[i], a, b);
            h[i] = a; l[i] = b;
        }
    } else {
        __shared__ float t[32][33];
        const int tt = blk - 256;
        const int bx = tt & 15, by = (tt >> 4) & 15, z = tt >> 8;
        const int b = z & 7;
        const float* src0 = (z < 8) ? x : y;
        bf16* d0 = (z < 8) ? xT : yT;
        const int c0 = by * 32, n0 = bx * 32;
        const int r = threadIdx.x >> 5, j = threadIdx.x & 31;
        const float* src = src0 + ((size_t)b * 512 + c0) * 512 + n0;
#pragma unroll
        for (int i = r; i < 32; i += 8) t[i][j] = src[(size_t)i * 512 + j];
        __syncthreads();
        const size_t dst = ((size_t)b * 512 + n0) * 512 + c0;
#pragma unroll
        for (int i = r; i < 32; i += 8) {
            bf16 a, bb;
            split2(t[j][i], a, bb);
            d0[0 * (size_t)XSZ + dst + (size_t)i * 512 + j] = a;
            d0[1 * (size_t)XSZ + dst + (size_t)i * 512 + j] = bb;
        }
    }
}

// ---------------- bf16 mma GEMM + BN + LIF (+ borderline flagging) ----------------
// D = A0*B0 + A0*B1 + A1*B0 (NB=2)  or  A0*B0 + A1*B0 (NB=1)
// 128x128 tile, BK=64, 8 stages, double-buffered cp.async, 256 threads (2x4 warps).
template<int NB, bool OUT_U8>
__device__ __forceinline__ void gemm_body(const bf16* __restrict__ A0, const bf16* __restrict__ A1,
                                          const bf16* __restrict__ B0, const bf16* __restrict__ B1,
                                          void* Out,
                                          const float* __restrict__ gam, const float* __restrict__ bet,
                                          const float* __restrict__ mean, const float* __restrict__ var,
                                          int bz, int stage, int which, char* sm) {
    const int NT = 2 + NB;                 // tiles per stage
    const int tid = threadIdx.x;
    const int lane = tid & 31, wid = tid >> 5;
    const int warp_m = wid & 1, warp_n = wid >> 1;
    const int row0 = blockIdx.y * 128, col0 = blockIdx.x * 128;
    const uint32_t sbase = smem_u32(sm);

    float acc[4][4][4];
#pragma unroll
    for (int i = 0; i < 4; i++)
#pragma unroll
        for (int j = 0; j < 4; j++)
#pragma unroll
            for (int q = 0; q < 4; q++) acc[i][j][q] = 0.0f;

    const bf16* srcs[4];
    srcs[0] = A0 + (size_t)row0 * 512;
    srcs[1] = A1 + (size_t)row0 * 512;
    srcs[2] = B0 + ((size_t)bz * 512 + col0) * 512;
    if (NB == 2) srcs[3] = B1 + ((size_t)bz * 512 + col0) * 512;

    // stage = NT tiles of [128][64] bf16; tile chunk (r, c): 16B at row r, chunk c^(r&7)
    auto issue = [&](int kt, int stg) {
        const uint32_t sb = sbase + stg * NT * 16384;
#pragma unroll
        for (int t = 0; t < NT; t++) {
            const bf16* base = srcs[t] + (kt << 6);
#pragma unroll
            for (int i = 0; i < 4; i++) {
                const int idx = tid + i * 256;
                const int r = idx >> 3, c = idx & 7;
                const uint32_t off = r * 128 + ((c ^ (r & 7)) << 4);
                cp16(sb + t * 16384 + off, base + (size_t)r * 512 + c * 8);
            }
        }
        cp_commit();
    };

    auto ldA = [&](uint32_t Af[4][4], uint32_t sA, int ks) {
#pragma unroll
        for (int tm = 0; tm < 4; tm++) {
            const int r = warp_m * 64 + tm * 16 + (lane & 15);
            const int ch = ks * 2 + (lane >> 4);
            ldmx4(Af[tm][0], Af[tm][1], Af[tm][2], Af[tm][3],
                  sA + r * 128 + ((ch ^ (r & 7)) << 4));
        }
    };
    auto ldB = [&](uint32_t Bf[2][4], uint32_t sB, int ks) {
#pragma unroll
        for (int tp = 0; tp < 2; tp++) {
            const int r = warp_n * 32 + tp * 16 + (lane & 7) + ((lane & 16) >> 1);
            const int ch = ks * 2 + ((lane >> 3) & 1);
            ldmx4(Bf[tp][0], Bf[tp][1], Bf[tp][2], Bf[tp][3],
                  sB + r * 128 + ((ch ^ (r & 7)) << 4));
        }
    };
    auto pass = [&](uint32_t Af[4][4], uint32_t Bf[2][4]) {
#pragma unroll
        for (int tm = 0; tm < 4; tm++)
#pragma unroll
            for (int tn = 0; tn < 4; tn++)
                mma_bf16(acc[tm][tn][0], acc[tm][tn][1], acc[tm][tn][2], acc[tm][tn][3],
                         Af[tm][0], Af[tm][1], Af[tm][2], Af[tm][3],
                         Bf[tn >> 1][(tn & 1) * 2], Bf[tn >> 1][(tn & 1) * 2 + 1]);
    };

    auto compute = [&](int stg) {
        const uint32_t sb = sbase + stg * NT * 16384;
#pragma unroll
        for (int ks = 0; ks < 4; ks++) {
            uint32_t Af0[4][4], Af1[4][4], Bf0[2][4];
            ldA(Af0, sb, ks);
            ldB(Bf0, sb + 2 * 16384, ks);
            ldA(Af1, sb + 16384, ks);
            if (NB == 2) {
                uint32_t Bf1[2][4];
                ldB(Bf1, sb + 3 * 16384, ks);
                pass(Af0, Bf0);
                pass(Af0, Bf1);
                pass(Af1, Bf0);
            } else {
                pass(Af0, Bf0);
                pass(Af1, Bf0);
            }
        }
    };

    issue(0, 0);
    for (int kt = 0; kt < 8; kt++) {
        if (kt + 1 < 8) { issue(kt + 1, (kt + 1) & 1); cp_wait<1>(); }
        else cp_wait<0>();
        __syncthreads();
        compute(kt & 1);
        __syncthreads();
    }

    // ---- epilogue: BN + LIF; flag borderline values for exact fp64 fixup ----
    const int r0l = lane >> 2, c0l = (lane & 3) * 2;
#pragma unroll
    for (int tm = 0; tm < 4; tm++) {
#pragma unroll
        for (int half = 0; half < 2; half++) {
            const int m = row0 + warp_m * 64 + tm * 16 + r0l + half * 8;
            const float invv = gam[m] / sqrtf(var[m] + 1e-5f);
            const float offv = bet[m] - mean[m] * invv;
            const size_t rowbase = ((size_t)bz * 512 + m) * 512 + col0 + warp_n * 32;
#pragma unroll
            for (int tn = 0; tn < 4; tn++) {
                const float bn0 = acc[tm][tn][half * 2 + 0] * invv + offv;
                const float bn1 = acc[tm][tn][half * 2 + 1] * invv + offv;
                const bool s0 = (bn0 >= 2.0f);
                const bool s1 = (bn1 >= 2.0f);
                const int ncol = col0 + warp_n * 32 + tn * 8 + c0l;
                if (fabsf(bn0 - 2.0f) < FLAGWIN) {
                    int ix = atomicAdd(&g_cnt[stage], 1);
                    if (ix < FIXCAP)
                        g_fix[stage][ix] = (uint32_t)which | ((uint32_t)bz << 2) |
                                           ((uint32_t)m << 5) | ((uint32_t)ncol << 14);
                }
                if (fabsf(bn1 - 2.0f) < FLAGWIN) {
                    int ix = atomicAdd(&g_cnt[stage], 1);
                    if (ix < FIXCAP)
                        g_fix[stage][ix] = (uint32_t)which | ((uint32_t)bz << 2) |
                                           ((uint32_t)m << 5) | ((uint32_t)(ncol + 1) << 14);
                }
                const size_t o = rowbase + tn * 8 + c0l;
                if (OUT_U8) {
                    *(unsigned short*)((uint8_t*)Out + o) =
                        (unsigned short)((s0 ? 1u : 0u) | ((s1 ? 1u : 0u) << 8));
                } else {
                    *(float2*)((float*)Out + o) = make_float2(s0 ? 1.f : 0.f, s1 ? 1.f : 0.f);
                }
            }
        }
    }
}

struct QKVp {
    const bf16 *A0[3], *A1[3], *B0[3], *B1[3];
    uint8_t* out[3];
    const float *gam[3], *bet[3], *mean[3], *var[3];
};

__global__ __launch_bounds__(256, 1) void gemm_qkv(QKVp P) {
    extern __shared__ char sm[];
    const int which = blockIdx.z >> 3;
    const int bz = blockIdx.z & 7;
    gemm_body<2, true>(P.A0[which], P.A1[which], P.B0[which], P.B1[which], P.out[which],
                       P.gam[which], P.bet[which], P.mean[which], P.var[which],
                       bz, 0, which, sm);
}

__global__ __launch_bounds__(256, 1) void gemm_proj(const bf16* A0, const bf16* A1,
                                                    const bf16* B0, float* Out,
                                                    const float* g, const float* b,
                                                    const float* m, const float* v) {
    extern __shared__ char sm[];
    gemm_body<1, false>(A0, A1, B0, B0, Out, g, b, m, v, blockIdx.z, 1, 0, sm);
}

// ---------------- exact fp64 fixup of borderline spikes ----------------
// ONE BLOCK PER ENTRY: 256 threads x 2 channels -> one memory round + 2-level reduce.
struct FixQ {
    const float* in[3];    // original [b][c][n]
    const float* w[3];
    const float *g[3], *be[3], *mn[3], *vr[3];
    uint8_t* out[3];
};

__global__ __launch_bounds__(256) void fixup_qkv(FixQ P) {
    __shared__ double red[8];
    const int cnt0 = g_cnt[0];
    const int cnt = cnt0 < FIXCAP ? cnt0 : FIXCAP;
    const int tid = threadIdx.x, lane = tid & 31, wid = tid >> 5;
    for (int e = blockIdx.x; e < cnt; e += gridDim.x) {
        const uint32_t t = g_fix[0][e];
        const int which = t & 3, b = (t >> 2) & 7, m = (t >> 5) & 511, n = (t >> 14) & 511;
        const float* W = P.w[which] + (size_t)m * 512;
        const float* X = P.in[which] + (size_t)b * 262144 + n;
        const float w0 = W[tid],        x0 = X[(size_t)tid * 512];
        const float w1 = W[tid + 256],  x1 = X[(size_t)(tid + 256) * 512];
        double s = (double)w0 * (double)x0 + (double)w1 * (double)x1;
#pragma unroll
        for (int o = 16; o; o >>= 1) s += __shfl_down_sync(0xffffffffu, s, o);
        if (lane == 0) red[wid] = s;
        __syncthreads();
        if (tid == 0) {
            double sum = red[0];
#pragma unroll
            for (int i = 1; i < 8; i++) sum += red[i];
            const double inv = (double)P.g[which][m] / sqrt((double)P.vr[which][m] + 1e-5);
            const double bn = sum * inv + ((double)P.be[which][m] - (double)P.mn[which][m] * inv);
            P.out[which][((size_t)b * 512 + m) * 512 + n] = (bn >= 2.0) ? (uint8_t)1 : (uint8_t)0;
        }
        __syncthreads();
    }
}

__global__ __launch_bounds__(256) void fixup_proj(const float* __restrict__ pw,
                                                  const bf16* __restrict__ sT, float* __restrict__ out,
                                                  const float* __restrict__ g, const float* __restrict__ be,
                                                  const float* __restrict__ mn, const float* __restrict__ vr) {
    __shared__ double red[8];
    const int cnt0 = g_cnt[1];
    const int cnt = cnt0 < FIXCAP ? cnt0 : FIXCAP;
    const int tid = threadIdx.x, lane = tid & 31, wid = tid >> 5;
    for (int e = blockIdx.x; e < cnt; e += gridDim.x) {
        const uint32_t t = g_fix[1][e];
        const int b = (t >> 2) & 7, m = (t >> 5) & 511, n = (t >> 14) & 511;
        const float* W = pw + (size_t)m * 512;
        const bf16* S = sT + ((size_t)b * 512 + n) * 512;
        const float w0 = W[tid],       x0 = __bfloat162float(S[tid]);
        const float w1 = W[tid + 256], x1 = __bfloat162float(S[tid + 256]);
        double s = (double)w0 * (double)x0 + (double)w1 * (double)x1;
#pragma unroll
        for (int o = 16; o; o >>= 1) s += __shfl_down_sync(0xffffffffu, s, o);
        if (lane == 0) red[wid] = s;
        __syncthreads();
        if (tid == 0) {
            double sum = red[0];
#pragma unroll
            for (int i = 1; i < 8; i++) sum += red[i];
            const double inv = (double)g[m] / sqrt((double)vr[m] + 1e-5);
            const double bn = sum * inv + ((double)be[m] - (double)mn[m] * inv);
            out[((size_t)b * 512 + m) * 512 + n] = (bn >= 2.0) ? 1.0f : 0.0f;
        }
        __syncthreads();
    }
}

// ---------------- spiking attention: o = Q (K^T V), bit-packed popc, exact ----------------
__global__ __launch_bounds__(512)
void attn_lif(const uint8_t* __restrict__ q, const uint8_t* __restrict__ k,
              const uint8_t* __restrict__ v, bf16* __restrict__ sT) {
    __shared__ uint32_t kb[32][17];   // K spike bits, padded vs bank conflicts
    __shared__ uint32_t vb[32][17];   // V spike bits
    __shared__ int M[32][33];

    const int tid = threadIdx.x;
    const int lane = tid & 31;
    const int tb = blockIdx.x >> 4;
    const int h = blockIdx.x & 15;
    const size_t base = ((size_t)tb * 512 + h * 32) * 512;

    // Pack K, V spike bytes (0/1) into bitmasks via warp ballot: 32 rows x 512 bits.
#pragma unroll
    for (int i = 0; i < 32; i++) {
        const unsigned bk = __ballot_sync(0xffffffffu, k[base + (size_t)i * 512 + tid] != 0);
        const unsigned bv = __ballot_sync(0xffffffffu, v[base + (size_t)i * 512 + tid] != 0);
        if (lane == 0) { kb[i][tid >> 5] = bk; vb[i][tid >> 5] = bv; }
    }
    __syncthreads();

    // M[dp][dd] = popc over 512 bits of (K row dp AND V row dd). 1024 entries, 2 per thread.
#pragma unroll
    for (int e = tid; e < 1024; e += 512) {
        const int dp = e >> 5, dd = e & 31;
        int acc = 0;
#pragma unroll
        for (int w = 0; w < 16; w++)
            acc += __popc(kb[dp][w] & vb[dd][w]);
        M[dp][dd] = acc;
    }
    __syncthreads();

    // o[n][d] = sum_dp q[dp][n] * M[dp][d]; spike = (o_int >= 8) (exact: *0.25/2 binary)
    const int n = tid;
    int oacc[32];
#pragma unroll
    for (int d = 0; d < 32; d++) oacc[d] = 0;
#pragma unroll 4
    for (int dp = 0; dp < 32; dp++) {
        if (q[base + (size_t)dp * 512 + n]) {
#pragma unroll
            for (int d = 0; d < 32; d++) oacc[d] += M[dp][d];
        }
    }
    uint32_t* dst = (uint32_t*)(sT + ((size_t)tb * 512 + n) * 512 + h * 32);
#pragma unroll
    for (int g = 0; g < 16; g++) {
        const uint32_t lo = (oacc[2 * g] >= 8) ? 0x3F80u : 0u;
        const uint32_t hi = (oacc[2 * g + 1] >= 8) ? 0x3F80u : 0u;
        dst[g] = lo | (hi << 16);
    }
}

// ---------------------------------------------------------------------------
extern "C" void kernel_launch(void* const* d_in, const int* in_sizes, int n_in,
                              void* d_out, int out_size) {
    (void)in_sizes; (void)n_in; (void)out_size;
    const float* x = (const float*)d_in[0];
    const float* y = (const float*)d_in[1];
    const float* w[4]  = {(const float*)d_in[2], (const float*)d_in[7], (const float*)d_in[12], (const float*)d_in[17]};
    const float* bg[4] = {(const float*)d_in[3], (const float*)d_in[8], (const float*)d_in[13], (const float*)d_in[18]};
    const float* bb[4] = {(const float*)d_in[4], (const float*)d_in[9], (const float*)d_in[14], (const float*)d_in[19]};
    const float* bm[4] = {(const float*)d_in[5], (const float*)d_in[10], (const float*)d_in[15], (const float*)d_in[20]};
    const float* bv[4] = {(const float*)d_in[6], (const float*)d_in[11], (const float*)d_in[16], (const float*)d_in[21]};

    bf16 *wsp, *xT, *yT, *sT;
    uint8_t *gq, *gk, *gv;
    cudaGetSymbolAddress((void**)&wsp, g_wsp);
    cudaGetSymbolAddress((void**)&xT, g_xT);
    cudaGetSymbolAddress((void**)&yT, g_yT);
    cudaGetSymbolAddress((void**)&sT, g_sT);
    cudaGetSymbolAddress((void**)&gq, g_q);
    cudaGetSymbolAddress((void**)&gk, g_k);
    cudaGetSymbolAddress((void**)&gv, g_v);

    cudaFuncSetAttribute(gemm_qkv, cudaFuncAttributeMaxDynamicSharedMemorySize, 131072);
    cudaFuncSetAttribute(gemm_proj, cudaFuncAttributeMaxDynamicSharedMemorySize, 98304);

    prep_all<<<4352, 256>>>(x, y, w[0], w[1], w[2], w[3], wsp, xT, yT);

    QKVp P;
    uint8_t* outs[3] = {gq, gk, gv};
    for (int g = 0; g < 3; g++) {
        P.A0[g] = wsp + (size_t)(g * 2 + 0) * WSZ;
        P.A1[g] = wsp + (size_t)(g * 2 + 1) * WSZ;
        P.B0[g] = (g == 0) ? xT : yT;
        P.B1[g] = ((g == 0) ? xT : yT) + (size_t)XSZ;
        P.out[g] = outs[g];
        P.gam[g] = bg[g]; P.bet[g] = bb[g]; P.mean[g] = bm[g]; P.var[g] = bv[g];
    }
    gemm_qkv<<<dim3(4, 4, 24), 256, 131072>>>(P);

    FixQ F;
    F.in[0] = x; F.in[1] = y; F.in[2] = y;
    for (int g = 0; g < 3; g++) {
        F.w[g] = w[g]; F.g[g] = bg[g]; F.be[g] = bb[g]; F.mn[g] = bm[g]; F.vr[g] = bv[g];
        F.out[g] = outs[g];
    }
    fixup_qkv<<<1024, 256>>>(F);

    attn_lif<<<128, 512>>>(gq, gk, gv, sT);

    gemm_proj<<<dim3(4, 4, 8), 256, 98304>>>(wsp + 6 * (size_t)WSZ, wsp + 7 * (size_t)WSZ,
                                             sT, (float*)d_out, bg[3], bb[3], bm[3], bv[3]);

    fixup_proj<<<1024, 256>>>(w[3], sT, (float*)d_out, bg[3], bb[3], bm[3], bv[3]);
}